// round 7
// baseline (speedup 1.0000x reference)
#include <cuda_runtime.h>
#include <cstdint>

#define NN 100096
#define FF 64
#define EB 128   // edges per scatter block

// ---------------- scratch (device globals: no runtime allocation) ----------
__device__ float g_sum_pos[(size_t)NN * FF];
__device__ float g_sum_neg[(size_t)NN * FF];
__device__ float g_cnt_pos[NN];
__device__ float g_cnt_neg[NN];
__device__ float g_mv[(size_t)NN * 256];   // matvec results: [node][Pp|Pc|Np|Nc]
__device__ float g_hb[136];                // hb_pos, hb_neg, y2_pos, y2_neg
__device__ float g_xn[NN];                 // ||x||      (clipped)
__device__ float g_pn[NN];                 // ||mean_p|| (clipped)
__device__ float g_nn[NN];                 // ||mean_n|| (clipped)

__device__ __forceinline__ float wsum(float v) {
#pragma unroll
    for (int o = 16; o > 0; o >>= 1) v += __shfl_xor_sync(0xffffffffu, v, o);
    return v;
}

// packed f32x2 helpers (sm_103a)
__device__ __forceinline__ unsigned long long fma2(unsigned long long a,
                                                   unsigned long long b,
                                                   unsigned long long c) {
    unsigned long long d;
    asm("fma.rn.f32x2 %0, %1, %2, %3;" : "=l"(d) : "l"(a), "l"(b), "l"(c));
    return d;
}
__device__ __forceinline__ unsigned long long pack2(float v) {
    unsigned long long d;
    asm("mov.b64 %0, {%1, %1};" : "=l"(d) : "r"(__float_as_uint(v)));
    return d;
}

// ---------------- shared GEMM inner body (256 nodes x 64 outs) -------------
// sA: [64][256] transposed inputs, sW: [64][68] transposed weights
__device__ __forceinline__ void gemm_body(const float* sA, const float* sW,
                                          float* mv, long node0, int n,
                                          int m_slot, int tid) {
    int og = tid & 7, ng = tid >> 3;
    unsigned long long acc[8][4];
#pragma unroll
    for (int i = 0; i < 8; ++i)
#pragma unroll
        for (int j = 0; j < 4; ++j) acc[i][j] = 0ull;

#pragma unroll 4
    for (int k = 0; k < 64; ++k) {
        float4 a0 = *reinterpret_cast<const float4*>(&sA[k * 256 + 4 * ng]);
        float4 a1 = *reinterpret_cast<const float4*>(&sA[k * 256 + 128 + 4 * ng]);
        ulonglong2 w0 = *reinterpret_cast<const ulonglong2*>(&sW[k * 68 + 8 * og]);
        ulonglong2 w1 = *reinterpret_cast<const ulonglong2*>(&sW[k * 68 + 8 * og + 4]);
        unsigned long long wv0 = w0.x, wv1 = w0.y, wv2 = w1.x, wv3 = w1.y;
        float av[8] = {a0.x, a0.y, a0.z, a0.w, a1.x, a1.y, a1.z, a1.w};
#pragma unroll
        for (int i = 0; i < 8; ++i) {
            unsigned long long p2 = pack2(av[i]);
            acc[i][0] = fma2(p2, wv0, acc[i][0]);
            acc[i][1] = fma2(p2, wv1, acc[i][1]);
            acc[i][2] = fma2(p2, wv2, acc[i][2]);
            acc[i][3] = fma2(p2, wv3, acc[i][3]);
        }
    }
#pragma unroll
    for (int i = 0; i < 8; ++i) {
        int node = (i < 4) ? (4 * ng + i) : (128 + 4 * ng + (i - 4));
        long gn = node0 + node;
        if (gn < n) {
            ulonglong2* dst = reinterpret_cast<ulonglong2*>(mv + gn * 256 + m_slot * 64 + 8 * og);
            dst[0] = make_ulonglong2(acc[i][0], acc[i][1]);
            dst[1] = make_ulonglong2(acc[i][2], acc[i][3]);
        }
    }
}

// ---------------- K1: fused scatter + cc-GEMM (m=1,3) + bias ---------------
__global__ void __launch_bounds__(256, 2)
fused1_kernel(const float* __restrict__ x,
              const float* __restrict__ Wpc, const float* __restrict__ Wnc,
              const float* __restrict__ bpc, const float* __restrict__ bnc,
              const int* __restrict__ pei, const int* __restrict__ nei,
              float* __restrict__ sp, float* __restrict__ sn,
              float* __restrict__ cp, float* __restrict__ cn,
              float* __restrict__ mv, int n, int E, int st, int Sp) {
    extern __shared__ float sh[];
    int bix = blockIdx.x, tid = threadIdx.x;

    if (bix % st == st - 1) {
        // ---- cc-GEMM block: operates on x only (independent of scatter) ----
        int g = bix / st;
        int m = (g & 1) ? 3 : 1;
        const float* W = (g & 1) ? Wnc : Wpc;
        long node0 = (long)(g >> 1) * 256;
        float* sA = sh;
        float* sW = sh + 64 * 256;
#pragma unroll
        for (int p = 0; p < 16; ++p) {
            int idx = p * 256 + tid;
            int o = idx >> 6, k = idx & 63;
            sW[k * 68 + o] = W[o * 64 + k];
        }
        {
            int nl = tid & 63, kc = tid >> 6;
#pragma unroll
            for (int q = 0; q < 4; ++q) {
                int node = q * 64 + nl;
                long gn = node0 + node;
                bool ok = gn < n;
                const float4* row = reinterpret_cast<const float4*>(x + (size_t)(ok ? gn : 0) * 64);
#pragma unroll
                for (int pk = 0; pk < 4; ++pk) {
                    int k4 = kc + 4 * pk;
                    float4 v = ok ? row[k4] : make_float4(0.f, 0.f, 0.f, 0.f);
                    sA[(4 * k4 + 0) * 256 + node] = v.x;
                    sA[(4 * k4 + 1) * 256 + node] = v.y;
                    sA[(4 * k4 + 2) * 256 + node] = v.z;
                    sA[(4 * k4 + 3) * 256 + node] = v.w;
                }
            }
        }
        __syncthreads();
        if (m == 1) {   // compute ||x|| once per node (m=1 blocks only)
            float acc = 0.f;
#pragma unroll
            for (int k = 0; k < 64; ++k) { float v = sA[k * 256 + tid]; acc = fmaf(v, v, acc); }
            long gn = node0 + tid;
            if (gn < n) g_xn[gn] = fmaxf(sqrtf(acc), 1e-15f);
        }
        gemm_body(sA, sW, mv, node0, n, m, tid);
        return;
    }

    int sid = bix - (bix + 1) / st;
    int S = 2 * Sp;
    if (sid < S) {
        // ---- scatter block ----
        __shared__ int s_src[EB], s_dst[EB];
        bool neg = sid >= Sp;
        const int* ei = neg ? nei : pei;
        float* sum = neg ? sn : sp;
        float* cnt = neg ? cn : cp;
        long base = (long)(neg ? sid - Sp : sid) * EB;
        if (tid < EB) {
            long e = base + tid;
            s_src[tid] = (e < E) ? ei[e] : -1;
        } else {
            long e = base + (tid - EB);
            s_dst[tid - EB] = (e < E) ? ei[(long)E + e] : -1;
        }
        __syncthreads();
        int ch = tid & 15, eg = tid >> 4;
#pragma unroll
        for (int it = 0; it < EB / 16; ++it) {
            int e = it * 16 + eg;
            int dst = s_dst[e];
            if (dst < 0) continue;
            int src = s_src[e];
            float4 v = *reinterpret_cast<const float4*>(x + (size_t)src * FF + ch * 4);
            float* a = sum + (size_t)dst * FF + ch * 4;
            asm volatile("red.global.add.v4.f32 [%0], {%1,%2,%3,%4};"
                         :: "l"(a), "f"(v.x), "f"(v.y), "f"(v.z), "f"(v.w) : "memory");
            if (ch == 0)
                asm volatile("red.global.add.f32 [%0], %1;" :: "l"(cnt + dst), "f"(1.0f) : "memory");
        }
    } else if (sid == S) {
        // ---- bias block: proj(expmap0(b, c=1)) ----
        if (tid < 32) {
            int lane = tid;
            const float* bs[2] = {bpc, bnc};
#pragma unroll
            for (int i = 0; i < 2; ++i) {
                float u0 = bs[i][lane], u1 = bs[i][lane + 32];
                float nb = fmaxf(sqrtf(wsum(u0 * u0 + u1 * u1)), 1e-15f);
                float s = tanhf(nb) / nb;
                float v0 = u0 * s, v1 = u1 * s;
                float vn = fmaxf(sqrtf(wsum(v0 * v0 + v1 * v1)), 1e-15f);
                if (vn > 0.996f) { float p = 0.996f / vn; v0 *= p; v1 *= p; }
                g_hb[i * 64 + lane]      = v0;
                g_hb[i * 64 + 32 + lane] = v1;
                float y2 = wsum(v0 * v0 + v1 * v1);
                if (lane == 0) g_hb[128 + i] = y2;
            }
        }
    }
}

// ---------------- K2: agg-GEMM (m=0,2) + mean norms ------------------------
__global__ void __launch_bounds__(256, 2)
gemm2_kernel(const float* __restrict__ Wp, const float* __restrict__ Wn,
             float* __restrict__ mv, int n) {
    extern __shared__ float sh[];
    float* sA = sh;
    float* sW = sh + 64 * 256;
    int by = blockIdx.y;
    int m = by ? 2 : 0;
    const float* W    = by ? Wn : Wp;
    const float* srcv = by ? g_sum_neg : g_sum_pos;
    const float* cnts = by ? g_cnt_neg : g_cnt_pos;
    long node0 = (long)blockIdx.x * 256;
    int tid = threadIdx.x;

#pragma unroll
    for (int p = 0; p < 16; ++p) {
        int idx = p * 256 + tid;
        int o = idx >> 6, k = idx & 63;
        sW[k * 68 + o] = W[o * 64 + k];
    }
    {
        int nl = tid & 63, kc = tid >> 6;
#pragma unroll
        for (int q = 0; q < 4; ++q) {
            int node = q * 64 + nl;
            long gn = node0 + node;
            bool ok = gn < n;
            long gc = ok ? gn : 0;
            float scale = 1.0f / fmaxf(cnts[gc], 1.0f);
            const float4* row = reinterpret_cast<const float4*>(srcv + (size_t)gc * 64);
#pragma unroll
            for (int pk = 0; pk < 4; ++pk) {
                int k4 = kc + 4 * pk;
                float4 v = ok ? row[k4] : make_float4(0.f, 0.f, 0.f, 0.f);
                sA[(4 * k4 + 0) * 256 + node] = v.x * scale;
                sA[(4 * k4 + 1) * 256 + node] = v.y * scale;
                sA[(4 * k4 + 2) * 256 + node] = v.z * scale;
                sA[(4 * k4 + 3) * 256 + node] = v.w * scale;
            }
        }
    }
    __syncthreads();
    {   // norm of the mean vector for node `tid`
        float acc = 0.f;
#pragma unroll
        for (int k = 0; k < 64; ++k) { float v = sA[k * 256 + tid]; acc = fmaf(v, v, acc); }
        long gn = node0 + tid;
        if (gn < n) (by ? g_nn : g_pn)[gn] = fmaxf(sqrtf(acc), 1e-15f);
    }
    gemm_body(sA, sW, mv, node0, n, m, tid);
}

// ---------------- K3: hyperbolic epilogue (warp per node) ------------------
// Scalar-norm algebra: ||tanh-scaled matvec|| = tanh(t); ||s||^2 = sn^2;
// ||q||^2 = (f1^2 x2 + 2 f1 f2 xy + f2^2 y2)/den^2 — no vector re-reductions.
__device__ __forceinline__ void node_out2(
    float aP0, float aP1, float pn,
    float aC0, float aC1, float xn,
    float hb0, float hb1, float y2,
    float& o0, float& o1) {
    float mnP = fmaxf(sqrtf(wsum(aP0 * aP0 + aP1 * aP1)), 1e-15f);
    float tP = tanhf(mnP / pn * atanhf(fminf(pn, 1.0f - 1e-7f)));
    float scP = fminf(tP, 0.996f) / mnP;
    float r0 = aP0 * scP, r1 = aP1 * scP;

    float mnC = fmaxf(sqrtf(wsum(aC0 * aC0 + aC1 * aC1)), 1e-15f);
    float tC = tanhf(mnC / xn * atanhf(fminf(xn, 1.0f - 1e-7f)));
    float sn_ = fminf(tC, 0.996f);
    float scC = sn_ / mnC;
    float s0 = aC0 * scC, s1 = aC1 * scC;

    float x2 = sn_ * sn_;
    float xy = wsum(s0 * hb0 + s1 * hb1);
    float f1 = 1.0f + 2.0f * xy + y2;
    float f2 = 1.0f - x2;
    float den = fmaxf(1.0f + 2.0f * xy + x2 * y2, 1e-15f);
    float inv = 1.0f / den;
    float q0 = (f1 * s0 + f2 * hb0) * inv;
    float q1 = (f1 * s1 + f2 * hb1) * inv;
    float qsq = fmaxf(f1 * f1 * x2 + 2.0f * f1 * f2 * xy + f2 * f2 * y2, 0.0f) * (inv * inv);
    float qn = fmaxf(sqrtf(qsq), 1e-15f);
    if (qn > 0.996f) { float p = 0.996f / qn; q0 *= p; q1 *= p; }
    o0 = r0 + q0; o1 = r1 + q1;
}

__global__ void epilogue_kernel(float* __restrict__ out, int n) {
    long w = (long)(blockIdx.x * blockDim.x + threadIdx.x) >> 5;
    int lane = threadIdx.x & 31;
    if (w >= n) return;

    const float* row = g_mv + (size_t)w * 256;
    float Pp0 = row[lane],       Pp1 = row[32 + lane];
    float Pc0 = row[64 + lane],  Pc1 = row[96 + lane];
    float Np0 = row[128 + lane], Np1 = row[160 + lane];
    float Nc0 = row[192 + lane], Nc1 = row[224 + lane];

    float xn = g_xn[w], pn = g_pn[w], nn = g_nn[w];
    float hbp0 = g_hb[lane],      hbp1 = g_hb[32 + lane];
    float hbn0 = g_hb[64 + lane], hbn1 = g_hb[96 + lane];
    float y2p = g_hb[128], y2n = g_hb[129];

    float oP0, oP1, oN0, oN1;
    node_out2(Pp0, Pp1, pn, Pc0, Pc1, xn, hbp0, hbp1, y2p, oP0, oP1);
    node_out2(Np0, Np1, nn, Nc0, Nc1, xn, hbn0, hbn1, y2n, oN0, oN1);

    out[w * 128 + lane]      = oP0;
    out[w * 128 + 32 + lane] = oP1;
    out[w * 128 + 64 + lane] = oN0;
    out[w * 128 + 96 + lane] = oN1;
}

// ---------------------------------------------------------------------------
extern "C" void kernel_launch(void* const* d_in, const int* in_sizes, int n_in,
                              void* d_out, int out_size) {
    const float* x   = (const float*)d_in[0];
    const float* Wp  = (const float*)d_in[1];
    const float* Wpc = (const float*)d_in[2];
    const float* bpc = (const float*)d_in[3];
    const float* Wn  = (const float*)d_in[4];
    const float* Wnc = (const float*)d_in[5];
    const float* bnc = (const float*)d_in[6];
    const int* pei   = (const int*)d_in[7];
    const int* nei   = (const int*)d_in[8];
    float* out = (float*)d_out;

    int n = in_sizes[0] / 64;
    int E = in_sizes[7] / 2;

    void *psum_p, *psum_n, *pcnt_p, *pcnt_n, *pmv;
    cudaGetSymbolAddress(&psum_p, g_sum_pos);
    cudaGetSymbolAddress(&psum_n, g_sum_neg);
    cudaGetSymbolAddress(&pcnt_p, g_cnt_pos);
    cudaGetSymbolAddress(&pcnt_n, g_cnt_neg);
    cudaGetSymbolAddress(&pmv, g_mv);
    cudaMemsetAsync(psum_p, 0, (size_t)n * 64 * sizeof(float));
    cudaMemsetAsync(psum_n, 0, (size_t)n * 64 * sizeof(float));
    cudaMemsetAsync(pcnt_p, 0, (size_t)n * sizeof(float));
    cudaMemsetAsync(pcnt_n, 0, (size_t)n * sizeof(float));

    // K1 grid: G gemm blocks interleaved every st-th slot among S scatter blocks + 1 bias
    int Sp = (E + EB - 1) / EB;          // scatter blocks per edge list
    int S = 2 * Sp;
    int G = 2 * ((n + 255) / 256);       // cc-gemm blocks (m=1 and m=3)
    int st = (S + G) / G + 1;            // ensures G*(st-1) >= S+1
    int grid1 = G * st;

    const int GSMEM = (64 * 256 + 64 * 68) * (int)sizeof(float); // 82,944 B
    cudaFuncSetAttribute(fused1_kernel, cudaFuncAttributeMaxDynamicSharedMemorySize, GSMEM);
    cudaFuncSetAttribute(gemm2_kernel, cudaFuncAttributeMaxDynamicSharedMemorySize, GSMEM);

    fused1_kernel<<<grid1, 256, GSMEM>>>(x, Wpc, Wnc, bpc, bnc, pei, nei,
                                         (float*)psum_p, (float*)psum_n,
                                         (float*)pcnt_p, (float*)pcnt_n,
                                         (float*)pmv, n, E, st, Sp);

    dim3 ggrid((n + 255) / 256, 2);
    gemm2_kernel<<<ggrid, 256, GSMEM>>>(Wp, Wn, (float*)pmv, n);

    int eblocks = (int)(((long)n * 32 + 255) / 256);
    epilogue_kernel<<<eblocks, 256>>>(out, n);
}

// round 10
// speedup vs baseline: 1.4410x; 1.4410x over previous
#include <cuda_runtime.h>
#include <cstdint>

#define NN 100096
#define FF 64
#define EB 128   // edges per scatter block

// ---------------- scratch (device globals: no runtime allocation) ----------
__device__ float g_sum_pos[(size_t)NN * FF];
__device__ float g_sum_neg[(size_t)NN * FF];
__device__ float g_cnt_pos[NN];
__device__ float g_cnt_neg[NN];
__device__ float g_mv[(size_t)NN * 256];   // matvec results: [node][Pp|Pc|Np|Nc]
__device__ float g_mvn[(size_t)NN * 4];    // matvec norms:   [node][m]  (clipped)
__device__ float g_hb[136];                // hb_pos, hb_neg, y2_pos, y2_neg
__device__ float g_xn[NN];                 // ||x||      (clipped)
__device__ float g_pn[NN];                 // ||mean_p|| (clipped)
__device__ float g_nn[NN];                 // ||mean_n|| (clipped)

__device__ __forceinline__ float wsum(float v) {
#pragma unroll
    for (int o = 16; o > 0; o >>= 1) v += __shfl_xor_sync(0xffffffffu, v, o);
    return v;
}

// packed f32x2 helpers (sm_103a)
__device__ __forceinline__ unsigned long long fma2(unsigned long long a,
                                                   unsigned long long b,
                                                   unsigned long long c) {
    unsigned long long d;
    asm("fma.rn.f32x2 %0, %1, %2, %3;" : "=l"(d) : "l"(a), "l"(b), "l"(c));
    return d;
}
__device__ __forceinline__ unsigned long long pack2(float v) {
    unsigned long long d;
    asm("mov.b64 %0, {%1, %1};" : "=l"(d) : "r"(__float_as_uint(v)));
    return d;
}
__device__ __forceinline__ float2 unpack2(unsigned long long a) {
    unsigned int lo, hi;
    asm("mov.b64 {%0, %1}, %2;" : "=r"(lo), "=r"(hi) : "l"(a));
    return make_float2(__uint_as_float(lo), __uint_as_float(hi));
}

// ---------------- bias: proj(expmap0(b, c=1)) ------------------------------
__global__ void bias_kernel(const float* __restrict__ bp, const float* __restrict__ bn) {
    int lane = threadIdx.x;
    if (lane >= 32) return;
    const float* bs[2] = {bp, bn};
#pragma unroll
    for (int i = 0; i < 2; ++i) {
        float u0 = bs[i][lane], u1 = bs[i][lane + 32];
        float nb = fmaxf(sqrtf(wsum(u0 * u0 + u1 * u1)), 1e-15f);
        float s = tanhf(nb) / nb;
        float v0 = u0 * s, v1 = u1 * s;
        float vn = fmaxf(sqrtf(wsum(v0 * v0 + v1 * v1)), 1e-15f);
        if (vn > 0.996f) { float p = 0.996f / vn; v0 *= p; v1 *= p; }
        g_hb[i * 64 + lane]      = v0;
        g_hb[i * 64 + 32 + lane] = v1;
        float y2 = wsum(v0 * v0 + v1 * v1);
        if (lane == 0) g_hb[128 + i] = y2;
    }
}

// ---------------- scatter: smem-staged indices, 16 threads/edge ------------
__global__ void scatter_kernel(const float* __restrict__ x,
                               const int* __restrict__ pei, const int* __restrict__ nei,
                               float* __restrict__ sp, float* __restrict__ sn,
                               float* __restrict__ cp, float* __restrict__ cn, int E) {
    __shared__ int s_src[EB], s_dst[EB];
    const int* ei = blockIdx.y ? nei : pei;
    float* sum = blockIdx.y ? sn : sp;
    float* cnt = blockIdx.y ? cn : cp;
    long base = (long)blockIdx.x * EB;
    int tid = threadIdx.x;
    if (tid < EB) {
        long e = base + tid;
        s_src[tid] = (e < E) ? ei[e] : -1;
    } else {
        long e = base + (tid - EB);
        s_dst[tid - EB] = (e < E) ? ei[(long)E + e] : -1;
    }
    __syncthreads();
    int ch = tid & 15, eg = tid >> 4;
#pragma unroll
    for (int it = 0; it < EB / 16; ++it) {
        int e = it * 16 + eg;
        int dst = s_dst[e];
        if (dst < 0) continue;
        int src = s_src[e];
        float4 v = *reinterpret_cast<const float4*>(x + (size_t)src * FF + ch * 4);
        float* a = sum + (size_t)dst * FF + ch * 4;
        asm volatile("red.global.add.v4.f32 [%0], {%1,%2,%3,%4};"
                     :: "l"(a), "f"(v.x), "f"(v.y), "f"(v.z), "f"(v.w) : "memory");
        if (ch == 0)
            asm volatile("red.global.add.f32 [%0], %1;" :: "l"(cnt + dst), "f"(1.0f) : "memory");
    }
}

// ---------------- unified GEMM: all four matrices, plus norms --------------
// block: 256 nodes x matrix m = blockIdx.y
// thread: og=tid&7 (8 outputs as 4 f32x2), ng=tid>>3 (8 nodes)
__global__ void __launch_bounds__(256, 2)
gemm_kernel(const float* __restrict__ x,
            const float* __restrict__ Wp,  const float* __restrict__ Wpc,
            const float* __restrict__ Wn,  const float* __restrict__ Wnc,
            float* __restrict__ mv, int n) {
    extern __shared__ float sh[];
    float* sA = sh;              // [64][256] transposed node vectors
    float* sW = sh + 64 * 256;   // [64][68]  transposed weights

    int m = blockIdx.y;
    const float* W = (m == 0) ? Wp : (m == 1) ? Wpc : (m == 2) ? Wn : Wnc;
    long node0 = (long)blockIdx.x * 256;
    int tid = threadIdx.x;

    // stage W transposed: sW[k*68+o] = W[o*64+k]
#pragma unroll
    for (int p = 0; p < 16; ++p) {
        int idx = p * 256 + tid;
        int o = idx >> 6, k = idx & 63;
        sW[k * 68 + o] = W[o * 64 + k];
    }
    // stage A transposed, mean-scaling folded in for m=0,2
    {
        int nl = tid & 63, kc = tid >> 6;
#pragma unroll
        for (int q = 0; q < 4; ++q) {
            int node = q * 64 + nl;
            long gn = node0 + node;
            bool ok = gn < n;
            long gc = ok ? gn : 0;
            const float* srcv;
            float scale = 1.0f;
            if (m & 1) srcv = x;
            else if (m == 0) { srcv = g_sum_pos; scale = 1.0f / fmaxf(g_cnt_pos[gc], 1.0f); }
            else             { srcv = g_sum_neg; scale = 1.0f / fmaxf(g_cnt_neg[gc], 1.0f); }
            const float4* row = reinterpret_cast<const float4*>(srcv + (size_t)gc * 64);
#pragma unroll
            for (int pk = 0; pk < 4; ++pk) {
                int k4 = kc + 4 * pk;
                float4 v = ok ? row[k4] : make_float4(0.f, 0.f, 0.f, 0.f);
                sA[(4 * k4 + 0) * 256 + node] = v.x * scale;
                sA[(4 * k4 + 1) * 256 + node] = v.y * scale;
                sA[(4 * k4 + 2) * 256 + node] = v.z * scale;
                sA[(4 * k4 + 3) * 256 + node] = v.w * scale;
            }
        }
    }
    __syncthreads();

    // input norms (m=0 -> pn, m=1 -> xn, m=2 -> nn), node `tid` column
    if (m < 3) {
        float acc = 0.f;
#pragma unroll
        for (int k = 0; k < 64; ++k) { float v = sA[k * 256 + tid]; acc = fmaf(v, v, acc); }
        long gn = node0 + tid;
        if (gn < n) {
            float* dst = (m == 0) ? g_pn : (m == 1) ? g_xn : g_nn;
            dst[gn] = fmaxf(sqrtf(acc), 1e-15f);
        }
    }

    int og = tid & 7, ng = tid >> 3;
    unsigned long long acc[8][4];
#pragma unroll
    for (int i = 0; i < 8; ++i)
#pragma unroll
        for (int j = 0; j < 4; ++j) acc[i][j] = 0ull;

#pragma unroll 4
    for (int k = 0; k < 64; ++k) {
        float4 a0 = *reinterpret_cast<const float4*>(&sA[k * 256 + 4 * ng]);
        float4 a1 = *reinterpret_cast<const float4*>(&sA[k * 256 + 128 + 4 * ng]);
        ulonglong2 w0 = *reinterpret_cast<const ulonglong2*>(&sW[k * 68 + 8 * og]);
        ulonglong2 w1 = *reinterpret_cast<const ulonglong2*>(&sW[k * 68 + 8 * og + 4]);
        unsigned long long wv0 = w0.x, wv1 = w0.y, wv2 = w1.x, wv3 = w1.y;
        float av[8] = {a0.x, a0.y, a0.z, a0.w, a1.x, a1.y, a1.z, a1.w};
#pragma unroll
        for (int i = 0; i < 8; ++i) {
            unsigned long long p2 = pack2(av[i]);
            acc[i][0] = fma2(p2, wv0, acc[i][0]);
            acc[i][1] = fma2(p2, wv1, acc[i][1]);
            acc[i][2] = fma2(p2, wv2, acc[i][2]);
            acc[i][3] = fma2(p2, wv3, acc[i][3]);
        }
    }

#pragma unroll
    for (int i = 0; i < 8; ++i) {
        int node = (i < 4) ? (4 * ng + i) : (128 + 4 * ng + (i - 4));
        long gn = node0 + node;
        // output-matvec squared norm: partial over this thread's 8 outputs,
        // reduced across the 8 og-lanes (lanes ng*8..ng*8+7 are consecutive)
        float ss = 0.f;
#pragma unroll
        for (int j = 0; j < 4; ++j) {
            float2 v = unpack2(acc[i][j]);
            ss = fmaf(v.x, v.x, fmaf(v.y, v.y, ss));
        }
#pragma unroll
        for (int o = 4; o > 0; o >>= 1) ss += __shfl_xor_sync(0xffffffffu, ss, o);
        if (gn < n) {
            ulonglong2* dst = reinterpret_cast<ulonglong2*>(mv + gn * 256 + m * 64 + 8 * og);
            dst[0] = make_ulonglong2(acc[i][0], acc[i][1]);
            dst[1] = make_ulonglong2(acc[i][2], acc[i][3]);
            if (og == 0) g_mvn[gn * 4 + m] = fmaxf(sqrtf(ss), 1e-15f);
        }
    }
}

// ---------------- hyperbolic epilogue (warp per node) ----------------------
// All norms precomputed; only 2 warp reductions (xy dot products) remain.
__device__ __forceinline__ void node_out3(
    float aP0, float aP1, float mnP, float pn,
    float aC0, float aC1, float mnC, float xn,
    float hb0, float hb1, float y2,
    float& o0, float& o1) {
    float tP = tanhf(mnP / pn * atanhf(fminf(pn, 1.0f - 1e-7f)));
    float scP = fminf(tP, 0.996f) / mnP;
    float r0 = aP0 * scP, r1 = aP1 * scP;

    float tC = tanhf(mnC / xn * atanhf(fminf(xn, 1.0f - 1e-7f)));
    float sn_ = fminf(tC, 0.996f);
    float scC = sn_ / mnC;
    float s0 = aC0 * scC, s1 = aC1 * scC;

    float x2 = sn_ * sn_;
    float xy = wsum(s0 * hb0 + s1 * hb1);
    float f1 = 1.0f + 2.0f * xy + y2;
    float f2 = 1.0f - x2;
    float den = fmaxf(1.0f + 2.0f * xy + x2 * y2, 1e-15f);
    float inv = 1.0f / den;
    float q0 = (f1 * s0 + f2 * hb0) * inv;
    float q1 = (f1 * s1 + f2 * hb1) * inv;
    float qsq = fmaxf(f1 * f1 * x2 + 2.0f * f1 * f2 * xy + f2 * f2 * y2, 0.0f) * (inv * inv);
    float qn = fmaxf(sqrtf(qsq), 1e-15f);
    if (qn > 0.996f) { float p = 0.996f / qn; q0 *= p; q1 *= p; }
    o0 = r0 + q0; o1 = r1 + q1;
}

__global__ void epilogue_kernel(float* __restrict__ out, int n) {
    long w = (long)(blockIdx.x * blockDim.x + threadIdx.x) >> 5;
    int lane = threadIdx.x & 31;
    if (w >= n) return;

    const float* row = g_mv + (size_t)w * 256;
    float Pp0 = row[lane],       Pp1 = row[32 + lane];
    float Pc0 = row[64 + lane],  Pc1 = row[96 + lane];
    float Np0 = row[128 + lane], Np1 = row[160 + lane];
    float Nc0 = row[192 + lane], Nc1 = row[224 + lane];

    float4 mn = *reinterpret_cast<const float4*>(g_mvn + (size_t)w * 4);
    float xn = g_xn[w], pn = g_pn[w], nn = g_nn[w];
    float hbp0 = g_hb[lane],      hbp1 = g_hb[32 + lane];
    float hbn0 = g_hb[64 + lane], hbn1 = g_hb[96 + lane];
    float y2p = g_hb[128], y2n = g_hb[129];

    float oP0, oP1, oN0, oN1;
    node_out3(Pp0, Pp1, mn.x, pn, Pc0, Pc1, mn.y, xn, hbp0, hbp1, y2p, oP0, oP1);
    node_out3(Np0, Np1, mn.z, nn, Nc0, Nc1, mn.w, xn, hbn0, hbn1, y2n, oN0, oN1);

    out[w * 128 + lane]      = oP0;
    out[w * 128 + 32 + lane] = oP1;
    out[w * 128 + 64 + lane] = oN0;
    out[w * 128 + 96 + lane] = oN1;
}

// ---------------------------------------------------------------------------
extern "C" void kernel_launch(void* const* d_in, const int* in_sizes, int n_in,
                              void* d_out, int out_size) {
    const float* x   = (const float*)d_in[0];
    const float* Wp  = (const float*)d_in[1];
    const float* Wpc = (const float*)d_in[2];
    const float* bpc = (const float*)d_in[3];
    const float* Wn  = (const float*)d_in[4];
    const float* Wnc = (const float*)d_in[5];
    const float* bnc = (const float*)d_in[6];
    const int* pei   = (const int*)d_in[7];
    const int* nei   = (const int*)d_in[8];
    float* out = (float*)d_out;

    int n = in_sizes[0] / 64;
    int E = in_sizes[7] / 2;

    void *psum_p, *psum_n, *pcnt_p, *pcnt_n, *pmv;
    cudaGetSymbolAddress(&psum_p, g_sum_pos);
    cudaGetSymbolAddress(&psum_n, g_sum_neg);
    cudaGetSymbolAddress(&pcnt_p, g_cnt_pos);
    cudaGetSymbolAddress(&pcnt_n, g_cnt_neg);
    cudaGetSymbolAddress(&pmv, g_mv);
    cudaMemsetAsync(psum_p, 0, (size_t)n * 64 * sizeof(float));
    cudaMemsetAsync(psum_n, 0, (size_t)n * 64 * sizeof(float));
    cudaMemsetAsync(pcnt_p, 0, (size_t)n * sizeof(float));
    cudaMemsetAsync(pcnt_n, 0, (size_t)n * sizeof(float));

    bias_kernel<<<1, 32>>>(bpc, bnc);

    dim3 sgrid((E + EB - 1) / EB, 2);
    scatter_kernel<<<sgrid, 256>>>(x, pei, nei,
                                   (float*)psum_p, (float*)psum_n,
                                   (float*)pcnt_p, (float*)pcnt_n, E);

    const int GSMEM = (64 * 256 + 64 * 68) * (int)sizeof(float); // 82,944 B
    cudaFuncSetAttribute(gemm_kernel, cudaFuncAttributeMaxDynamicSharedMemorySize, GSMEM);
    dim3 ggrid((n + 255) / 256, 4);
    gemm_kernel<<<ggrid, 256, GSMEM>>>(x, Wp, Wpc, Wn, Wnc, (float*)pmv, n);

    int eblocks = (int)(((long)n * 32 + 255) / 256);
    epilogue_kernel<<<eblocks, 256>>>(out, n);
}